// round 2
// baseline (speedup 1.0000x reference)
#include <cuda_runtime.h>
#include <cuda_bf16.h>
#include <math.h>

// Problem constants (fixed shapes per reference)
#define NN 100000
#define NE 3200000
#define HH 64
#define NG 128

// Scratch (static __device__ arrays — no allocation allowed)
__device__ float d_deg[NN];
__device__ float d_hs[NN * HH];    // h * dinv  (message payload)
__device__ float d_acc[NN * HH];   // scatter accumulator
__device__ float d_x[NN * HH];     // layer activations
__device__ float d_gsum[NG * HH];  // pooled sums
__device__ int   d_gcnt[NG];       // pooled counts

// ---------------------------------------------------------------------------
// Zero deg / gsum / gcnt
__global__ void k_init() {
    int i = blockIdx.x * blockDim.x + threadIdx.x;
    if (i < NN) d_deg[i] = 0.f;
    if (i < NG * HH) d_gsum[i] = 0.f;
    if (i < NG) d_gcnt[i] = 0;
}

// ---------------------------------------------------------------------------
// deg[dst] += ew   (weighted in-degree; +1 self-loop folded into rsqrt later)
__global__ void k_deg(const int* __restrict__ dst, const float* __restrict__ ew,
                      int E) {
    int i = blockIdx.x * blockDim.x + threadIdx.x;
    if (i < E) atomicAdd(&d_deg[dst[i]], ew[i]);
}

// ---------------------------------------------------------------------------
// Node GEMM: hs[n] = (x[n] @ W) * dinv[n];  also zeroes acc for the layer.
// 16 nodes per 256-thread block. LAYER1 gathers x from emb[labels].
template <bool LAYER1>
__global__ void k_node(const int* __restrict__ labels,
                       const float* __restrict__ emb,
                       const float* __restrict__ W) {
    __shared__ float Ws[HH][HH];       // 16KB
    __shared__ float xs[16][HH + 1];   // padded
    const int nb = blockIdx.x * 16;

    for (int i = threadIdx.x; i < HH * HH; i += 256)
        Ws[i >> 6][i & 63] = W[i];
    for (int i = threadIdx.x; i < 16 * HH; i += 256) {
        int ln = i >> 6, c = i & 63;
        int n = nb + ln;
        float v = 0.f;
        if (n < NN) {
            if (LAYER1) v = emb[labels[n] * HH + c];
            else        v = d_x[n * HH + c];
        }
        xs[ln][c] = v;
    }
    __syncthreads();

    const int c = threadIdx.x & 63;
    const int g = threadIdx.x >> 6;   // 0..3, handles local nodes g*4..g*4+3
    float acc[4] = {0.f, 0.f, 0.f, 0.f};
#pragma unroll
    for (int k = 0; k < HH; k++) {
        float w = Ws[k][c];
#pragma unroll
        for (int j = 0; j < 4; j++) acc[j] += xs[g * 4 + j][k] * w;
    }
#pragma unroll
    for (int j = 0; j < 4; j++) {
        int n = nb + g * 4 + j;
        if (n < NN) {
            float dv = rsqrtf(d_deg[n] + 1.0f);
            d_hs[n * HH + c]  = acc[j] * dv;
            d_acc[n * HH + c] = 0.f;
        }
    }
}

// ---------------------------------------------------------------------------
// Edge scatter: acc[dst] += hs[src] * ew.  2 edges per warp, 16 lanes/edge,
// float4 gather + red.global.add.v4.f32 (4x fewer RED lane-ops).
__global__ void k_scatter(const int* __restrict__ src,
                          const int* __restrict__ dst,
                          const float* __restrict__ ew, int E) {
    int gtid = blockIdx.x * blockDim.x + threadIdx.x;
    int warp = gtid >> 5;
    int half = (threadIdx.x >> 4) & 1;
    int l4 = threadIdx.x & 15;
    long e = (long)warp * 2 + half;
    if (e >= E) return;

    int s = src[e];
    int d = dst[e];
    float w = ew[e];

    const float4* hp = reinterpret_cast<const float4*>(d_hs + (size_t)s * HH);
    float4 v = hp[l4];
    v.x *= w; v.y *= w; v.z *= w; v.w *= w;

    float* ap = d_acc + (size_t)d * HH + l4 * 4;
    asm volatile("red.global.add.v4.f32 [%0], {%1,%2,%3,%4};"
                 :: "l"(ap), "f"(v.x), "f"(v.y), "f"(v.z), "f"(v.w)
                 : "memory");
}

// ---------------------------------------------------------------------------
// Finalize layer 1: x = relu(dinv*(acc + hs) + b); re-zero acc for layer 2.
__global__ void k_fin1(const float* __restrict__ b) {
    int idx = blockIdx.x * blockDim.x + threadIdx.x;
    if (idx >= NN * HH) return;
    int n = idx >> 6, c = idx & 63;
    float dv = rsqrtf(d_deg[n] + 1.0f);
    float v = dv * (d_acc[idx] + d_hs[idx]) + b[c];
    d_x[idx] = fmaxf(v, 0.f);
    d_acc[idx] = 0.f;
}

// ---------------------------------------------------------------------------
// Finalize layer 2 + pool: atomically accumulate relu output into graph sums.
__global__ void k_fin2_pool(const float* __restrict__ b,
                            const int* __restrict__ batch) {
    int idx = blockIdx.x * blockDim.x + threadIdx.x;
    if (idx >= NN * HH) return;
    int n = idx >> 6, c = idx & 63;
    float dv = rsqrtf(d_deg[n] + 1.0f);
    float v = fmaxf(dv * (d_acc[idx] + d_hs[idx]) + b[c], 0.f);
    int g = batch[n];
    atomicAdd(&d_gsum[g * HH + c], v);
    if (c == 0) atomicAdd(&d_gcnt[g], 1);
}

// ---------------------------------------------------------------------------
// Head: mean -> relu(g@W3+b3) -> @W4+b4.  One 64-thread block per graph.
__global__ void k_head(const float* __restrict__ W3, const float* __restrict__ b3,
                       const float* __restrict__ W4, const float* __restrict__ b4,
                       float* __restrict__ out) {
    __shared__ float mean[HH];
    __shared__ float red[HH];
    int g = blockIdx.x, c = threadIdx.x;
    float cnt = fmaxf((float)d_gcnt[g], 1.0f);
    mean[c] = d_gsum[g * HH + c] / cnt;
    __syncthreads();
    float a = 0.f;
#pragma unroll
    for (int k = 0; k < HH; k++) a += mean[k] * W3[k * HH + c];
    float t = fmaxf(a + b3[c], 0.f);
    red[c] = t * W4[c];
    __syncthreads();
    for (int s = 32; s > 0; s >>= 1) {
        if (c < s) red[c] += red[c + s];
        __syncthreads();
    }
    if (c == 0) out[g] = red[0] + b4[0];
}

// ---------------------------------------------------------------------------
extern "C" void kernel_launch(void* const* d_in, const int* in_sizes, int n_in,
                              void* d_out, int out_size) {
    const int*   labels = (const int*)d_in[0];
    const int*   eidx   = (const int*)d_in[1];   // [2, E]
    const float* ew     = (const float*)d_in[2];
    const int*   batch  = (const int*)d_in[3];
    const float* emb    = (const float*)d_in[4];
    const float* W1 = (const float*)d_in[5];
    const float* b1 = (const float*)d_in[6];
    const float* W2 = (const float*)d_in[7];
    const float* b2 = (const float*)d_in[8];
    const float* W3 = (const float*)d_in[9];
    const float* b3 = (const float*)d_in[10];
    const float* W4 = (const float*)d_in[11];
    const float* b4 = (const float*)d_in[12];
    float* out = (float*)d_out;

    const int E = in_sizes[2];           // 3,200,000
    const int* src = eidx;
    const int* dst = eidx + E;

    const int TB = 256;
    const int initBlocks = (NN + TB - 1) / TB;
    const int degBlocks  = (E + TB - 1) / TB;
    const int nodeBlocks = (NN + 15) / 16;
    const int elemBlocks = (NN * HH + TB - 1) / TB;
    // 2 edges per warp -> 16 edges per 256-thread block
    const int scatBlocks = (E + 15) / 16;

    k_init<<<initBlocks, TB>>>();
    k_deg<<<degBlocks, TB>>>(dst, ew, E);

    // Layer 1
    k_node<true><<<nodeBlocks, TB>>>(labels, emb, W1);
    k_scatter<<<scatBlocks, TB>>>(src, dst, ew, E);
    k_fin1<<<elemBlocks, TB>>>(b1);

    // Layer 2
    k_node<false><<<nodeBlocks, TB>>>(labels, emb, W2);
    k_scatter<<<scatBlocks, TB>>>(src, dst, ew, E);
    k_fin2_pool<<<elemBlocks, TB>>>(b2, batch);

    // Head
    k_head<<<NG, HH>>>(W3, b3, W4, b4, out);
}

// round 3
// speedup vs baseline: 1.0425x; 1.0425x over previous
#include <cuda_runtime.h>
#include <cuda_bf16.h>
#include <math.h>

#define NN 100000
#define NE 3200000
#define HH 64
#define NG 128
#define FULL 0xffffffffu

// Static scratch (no allocation allowed)
__device__ float d_deg[NN];          // weighted in-degree
__device__ int   d_cnt[NN];          // edge count per dst
__device__ int   d_off[NN + 1];      // CSR row offsets
__device__ int   d_cur[NN];          // scatter cursors
__device__ int   d_es[NE];           // src sorted by dst
__device__ float d_ew2[NE];          // weight sorted by dst
__device__ float d_hs[NN * HH];      // (x @ W) * dinv
__device__ float d_x[NN * HH];       // layer activations
__device__ float d_gsum[NG * HH];
__device__ int   d_gcnt[NG];

// ---------------------------------------------------------------------------
__global__ void k_init() {
    int i = blockIdx.x * blockDim.x + threadIdx.x;
    if (i < NN) { d_deg[i] = 0.f; d_cnt[i] = 0; }
    if (i < NG * HH) d_gsum[i] = 0.f;
    if (i < NG) d_gcnt[i] = 0;
}

// Histogram: edge count + weighted degree per dst
__global__ void k_hist(const int* __restrict__ dst, const float* __restrict__ ew,
                       int E) {
    int i = blockIdx.x * blockDim.x + threadIdx.x;
    if (i < E) {
        int d = dst[i];
        atomicAdd(&d_cnt[d], 1);
        atomicAdd(&d_deg[d], ew[i]);
    }
}

// Single-block exclusive scan over d_cnt (4096 elems/tile, warp-shuffle scan)
__global__ void k_scan() {
    __shared__ int wsum[32];
    __shared__ int carry;
    const int tid = threadIdx.x;        // 1024 threads
    const int lane = tid & 31, wid = tid >> 5;
    if (tid == 0) carry = 0;
    __syncthreads();
    for (int base = 0; base < NN; base += 4096) {
        int idx = base + tid * 4;
        int v0 = (idx + 0 < NN) ? d_cnt[idx + 0] : 0;
        int v1 = (idx + 1 < NN) ? d_cnt[idx + 1] : 0;
        int v2 = (idx + 2 < NN) ? d_cnt[idx + 2] : 0;
        int v3 = (idx + 3 < NN) ? d_cnt[idx + 3] : 0;
        int s0 = v0, s1 = s0 + v1, s2 = s1 + v2, s3 = s2 + v3;
        int incl = s3;
#pragma unroll
        for (int off = 1; off < 32; off <<= 1) {
            int t = __shfl_up_sync(FULL, incl, off);
            if (lane >= off) incl += t;
        }
        if (lane == 31) wsum[wid] = incl;
        __syncthreads();
        if (wid == 0) {
            int t = wsum[lane];
#pragma unroll
            for (int off = 1; off < 32; off <<= 1) {
                int u = __shfl_up_sync(FULL, t, off);
                if (lane >= off) t += u;
            }
            wsum[lane] = t;
        }
        __syncthreads();
        int warp_excl = (wid == 0) ? 0 : wsum[wid - 1];
        int excl = carry + warp_excl + (incl - s3);
        if (idx + 0 < NN) { d_off[idx + 0] = excl;      d_cur[idx + 0] = excl; }
        if (idx + 1 < NN) { d_off[idx + 1] = excl + s0; d_cur[idx + 1] = excl + s0; }
        if (idx + 2 < NN) { d_off[idx + 2] = excl + s1; d_cur[idx + 2] = excl + s1; }
        if (idx + 3 < NN) { d_off[idx + 3] = excl + s2; d_cur[idx + 3] = excl + s2; }
        __syncthreads();
        if (tid == 1023) carry += wsum[31];
        __syncthreads();
    }
    if (tid == 0) d_off[NN] = carry;
}

// Counting-sort edges by dst
__global__ void k_reorder(const int* __restrict__ src, const int* __restrict__ dst,
                          const float* __restrict__ ew, int E) {
    int i = blockIdx.x * blockDim.x + threadIdx.x;
    if (i >= E) return;
    int d = dst[i];
    int p = atomicAdd(&d_cur[d], 1);
    d_es[p] = src[i];
    d_ew2[p] = ew[i];
}

// ---------------------------------------------------------------------------
// Node GEMM: hs[n] = (x[n] @ W) * dinv[n]. 16 nodes per 256-thread block.
template <bool LAYER1>
__global__ void k_node(const int* __restrict__ labels,
                       const float* __restrict__ emb,
                       const float* __restrict__ W) {
    __shared__ float Ws[HH][HH];
    __shared__ float xs[16][HH + 1];
    const int nb = blockIdx.x * 16;

    for (int i = threadIdx.x; i < HH * HH; i += 256)
        Ws[i >> 6][i & 63] = W[i];
    for (int i = threadIdx.x; i < 16 * HH; i += 256) {
        int ln = i >> 6, c = i & 63;
        int n = nb + ln;
        float v = 0.f;
        if (n < NN) {
            if (LAYER1) v = emb[labels[n] * HH + c];
            else        v = d_x[n * HH + c];
        }
        xs[ln][c] = v;
    }
    __syncthreads();

    const int c = threadIdx.x & 63;
    const int g = threadIdx.x >> 6;
    float acc[4] = {0.f, 0.f, 0.f, 0.f};
#pragma unroll
    for (int k = 0; k < HH; k++) {
        float w = Ws[k][c];
#pragma unroll
        for (int j = 0; j < 4; j++) acc[j] += xs[g * 4 + j][k] * w;
    }
#pragma unroll
    for (int j = 0; j < 4; j++) {
        int n = nb + g * 4 + j;
        if (n < NN) {
            float dv = rsqrtf(d_deg[n] + 1.0f);
            d_hs[n * HH + c] = acc[j] * dv;
        }
    }
}

// ---------------------------------------------------------------------------
// CSR gather: one warp per node, float2 per lane, metadata broadcast via shfl.
// PHASE 1: write relu activation to d_x.  PHASE 2: pool into d_gsum/d_gcnt.
template <int PHASE>
__global__ void k_gather(const float* __restrict__ b,
                         const int* __restrict__ batch) {
    const int n = (blockIdx.x * blockDim.x + threadIdx.x) >> 5;
    const int lane = threadIdx.x & 31;
    if (n >= NN) return;
    const int beg = d_off[n], end = d_off[n + 1];
    const float2* __restrict__ hs2 = reinterpret_cast<const float2*>(d_hs);

    float ax = 0.f, ay = 0.f;
    int i = beg;
    for (; i + 32 <= end; i += 32) {
        int   s_l = d_es[i + lane];
        float w_l = d_ew2[i + lane];
#pragma unroll 8
        for (int j = 0; j < 32; j++) {
            int   s = __shfl_sync(FULL, s_l, j);
            float w = __shfl_sync(FULL, w_l, j);
            float2 v = hs2[(size_t)s * 32 + lane];
            ax = fmaf(w, v.x, ax);
            ay = fmaf(w, v.y, ay);
        }
    }
    int rem = end - i;
    if (rem > 0) {
        int   s_l = 0; float w_l = 0.f;
        if (lane < rem) { s_l = d_es[i + lane]; w_l = d_ew2[i + lane]; }
        for (int j = 0; j < rem; j++) {
            int   s = __shfl_sync(FULL, s_l, j);
            float w = __shfl_sync(FULL, w_l, j);
            float2 v = hs2[(size_t)s * 32 + lane];
            ax = fmaf(w, v.x, ax);
            ay = fmaf(w, v.y, ay);
        }
    }

    float2 h = hs2[(size_t)n * 32 + lane];
    float dv = rsqrtf(d_deg[n] + 1.0f);
    float vx = fmaxf(dv * (ax + h.x) + b[lane * 2],     0.f);
    float vy = fmaxf(dv * (ay + h.y) + b[lane * 2 + 1], 0.f);

    if (PHASE == 1) {
        reinterpret_cast<float2*>(d_x)[(size_t)n * 32 + lane] = make_float2(vx, vy);
    } else {
        int g = batch[n];  // uniform across warp
        atomicAdd(&d_gsum[g * HH + lane * 2],     vx);
        atomicAdd(&d_gsum[g * HH + lane * 2 + 1], vy);
        if (lane == 0) atomicAdd(&d_gcnt[g], 1);
    }
}

// ---------------------------------------------------------------------------
__global__ void k_head(const float* __restrict__ W3, const float* __restrict__ b3,
                       const float* __restrict__ W4, const float* __restrict__ b4,
                       float* __restrict__ out) {
    __shared__ float mean[HH];
    __shared__ float red[HH];
    int g = blockIdx.x, c = threadIdx.x;
    float cnt = fmaxf((float)d_gcnt[g], 1.0f);
    mean[c] = d_gsum[g * HH + c] / cnt;
    __syncthreads();
    float a = 0.f;
#pragma unroll
    for (int k = 0; k < HH; k++) a += mean[k] * W3[k * HH + c];
    float t = fmaxf(a + b3[c], 0.f);
    red[c] = t * W4[c];
    __syncthreads();
    for (int s = 32; s > 0; s >>= 1) {
        if (c < s) red[c] += red[c + s];
        __syncthreads();
    }
    if (c == 0) out[g] = red[0] + b4[0];
}

// ---------------------------------------------------------------------------
extern "C" void kernel_launch(void* const* d_in, const int* in_sizes, int n_in,
                              void* d_out, int out_size) {
    const int*   labels = (const int*)d_in[0];
    const int*   eidx   = (const int*)d_in[1];
    const float* ew     = (const float*)d_in[2];
    const int*   batch  = (const int*)d_in[3];
    const float* emb    = (const float*)d_in[4];
    const float* W1 = (const float*)d_in[5];
    const float* b1 = (const float*)d_in[6];
    const float* W2 = (const float*)d_in[7];
    const float* b2 = (const float*)d_in[8];
    const float* W3 = (const float*)d_in[9];
    const float* b3 = (const float*)d_in[10];
    const float* W4 = (const float*)d_in[11];
    const float* b4 = (const float*)d_in[12];
    float* out = (float*)d_out;

    const int E = in_sizes[2];
    const int* src = eidx;
    const int* dst = eidx + E;

    const int TB = 256;
    const int initBlocks = (NN + TB - 1) / TB;
    const int edgeBlocks = (E + TB - 1) / TB;
    const int nodeBlocks = (NN + 15) / 16;
    const int gathBlocks = (NN + 7) / 8;   // 8 warps per block, 1 node/warp

    // CSR build (once; reused by both layers)
    k_init<<<initBlocks, TB>>>();
    k_hist<<<edgeBlocks, TB>>>(dst, ew, E);
    k_scan<<<1, 1024>>>();
    k_reorder<<<edgeBlocks, TB>>>(src, dst, ew, E);

    // Layer 1
    k_node<true><<<nodeBlocks, TB>>>(labels, emb, W1);
    k_gather<1><<<gathBlocks, TB>>>(b1, batch);

    // Layer 2
    k_node<false><<<nodeBlocks, TB>>>(labels, emb, W2);
    k_gather<2><<<gathBlocks, TB>>>(b2, batch);

    // Head
    k_head<<<NG, HH>>>(W3, b3, W4, b4, out);
}